// round 13
// baseline (speedup 1.0000x reference)
#include <cuda_runtime.h>
#include <cuda_fp16.h>
#include <math.h>
#include <string.h>
#include <stdint.h>

#define TOKENS 4096
#define SEQLEN 2048
#define NB 2
#define DM 2048
#define NH 16
#define QLORA 1536
#define KVLORA 512
#define NOPE 128
#define ROPE 64
#define DQK 192
#define DV 128
#define DFF 8192
#define NQKVD (QLORA + KVLORA + ROPE)   // 2112

typedef __half h16;

// fp32 scratch (residual stream only)
__device__ float g_x[TOKENS * DM];
// fp16 activations
__device__ h16 g_hf[TOKENS * DM];
__device__ h16 g_qkvl[TOKENS * NQKVD];
__device__ h16 g_qlnf[TOKENS * QLORA];
__device__ h16 g_kvnf[TOKENS * KVLORA];
__device__ h16 g_qh[TOKENS * NH * DQK];
__device__ h16 g_kvh[TOKENS * NH * (NOPE + DV)];
__device__ h16 g_krope[TOKENS * ROPE];
__device__ h16 g_h2[TOKENS * DM];
__device__ h16 g_gateh[TOKENS * DFF];
__device__ h16 g_ff[TOKENS * DFF];
__device__ h16 g_Qf[TOKENS * NH * DQK];
__device__ h16 g_Kf[TOKENS * NH * DQK];
__device__ h16 g_Vf[TOKENS * NH * DV];
__device__ h16 g_atf[TOKENS * NH * DV];
// fp16 weights [K][N]
__device__ h16 g_wqkvd[DM * NQKVD];
__device__ h16 g_wqu[QLORA * (NH * DQK)];
__device__ h16 g_wkvu[KVLORA * (NH * (NOPE + DV))];
__device__ h16 g_wo[(NH * DV) * DM];
__device__ h16 g_wg[DM * DFF];
__device__ h16 g_wu[DM * DFF];
__device__ h16 g_wd[DFF * DM];

// ==================== PTX helpers ====================
__device__ __forceinline__ uint32_t smem_u32(const void* p) {
    uint32_t a;
    asm("{ .reg .u64 t; cvta.to.shared.u64 t, %1; cvt.u32.u64 %0, t; }" : "=r"(a) : "l"(p));
    return a;
}
__device__ __forceinline__ void cp16(uint32_t d, const void* s, int sz) {
    asm volatile("cp.async.cg.shared.global [%0], [%1], 16, %2;" :: "r"(d), "l"(s), "r"(sz) : "memory");
}
__device__ __forceinline__ void cp_commit() { asm volatile("cp.async.commit_group;" ::: "memory"); }
__device__ __forceinline__ void cp_wait0() { asm volatile("cp.async.wait_group 0;" ::: "memory"); }
__device__ __forceinline__ void cp_wait1() { asm volatile("cp.async.wait_group 1;" ::: "memory"); }
__device__ __forceinline__ void ldsm4(uint32_t* r, uint32_t a) {
    asm volatile("ldmatrix.sync.aligned.m8n8.x4.shared.b16 {%0, %1, %2, %3}, [%4];"
                 : "=r"(r[0]), "=r"(r[1]), "=r"(r[2]), "=r"(r[3]) : "r"(a));
}
__device__ __forceinline__ void ldsm4t(uint32_t* r, uint32_t a) {
    asm volatile("ldmatrix.sync.aligned.m8n8.x4.trans.shared.b16 {%0, %1, %2, %3}, [%4];"
                 : "=r"(r[0]), "=r"(r[1]), "=r"(r[2]), "=r"(r[3]) : "r"(a));
}
__device__ __forceinline__ void mma_f16(float* c, const uint32_t* a, const uint32_t* b) {
    asm volatile(
        "mma.sync.aligned.m16n8k16.row.col.f32.f16.f16.f32 "
        "{%0, %1, %2, %3}, {%4, %5, %6, %7}, {%8, %9}, {%0, %1, %2, %3};"
        : "+f"(c[0]), "+f"(c[1]), "+f"(c[2]), "+f"(c[3])
        : "r"(a[0]), "r"(a[1]), "r"(a[2]), "r"(a[3]), "r"(b[0]), "r"(b[1]));
}
__device__ __forceinline__ uint32_t pack2h(float a, float b) {
    __half2 h = __floats2half2_rn(a, b);
    uint32_t u;
    memcpy(&u, &h, 4);
    return u;
}

// ==================== GEMM tiling: BK=64, 2 stages, 2 CTA/SM (round-12 proven) ====================
#define ASTR2 72
#define A2_BYTES (128 * ASTR2 * 2)
#define B2_BYTES (64 * 136 * 2)
#define OFF2_B A2_BYTES
#define STAGE2 (A2_BYTES + B2_BYTES)
#define GEMM_SMEM2 (2 * STAGE2)

// mode 0: C(fp32) = acc (+Df); mode 1: Cs(fp16) = silu(Dh)*acc; mode 2: Cs = acc
__global__ __launch_bounds__(256, 2) void h1gemm(
    const h16* __restrict__ A, const h16* __restrict__ B,
    const float* __restrict__ Df, const h16* __restrict__ Dh,
    float* __restrict__ C, h16* __restrict__ Cs,
    int mode, int M, int N, int K) {
    extern __shared__ __align__(128) char sm[];
    const int tid = threadIdx.x, wid = tid >> 5, lane = tid & 31;
    const int row0 = blockIdx.y * 128, col0 = blockIdx.x * 128;
    const int m0w = (wid >> 1) * 32, n0w = (wid & 1) * 64;
    const uint32_t smb = smem_u32(sm);

    auto load_stage = [&](int s, int k0) {
        uint32_t sb = smb + (uint32_t)s * STAGE2;
#pragma unroll
        for (int p = 0; p < 4; p++) {
            int idx = tid + p * 256;
            int r = idx >> 3, ch = idx & 7;
            cp16(sb + (uint32_t)(r * 144 + ch * 16),
                 A + (size_t)(row0 + r) * K + k0 + ch * 8, 16);
        }
#pragma unroll
        for (int p = 0; p < 4; p++) {
            int idx = tid + p * 256;
            int r = idx >> 4, ch = idx & 15;
            int col = col0 + ch * 8;
            int valid = (col < N) ? 16 : 0;
            int colc = (col < N) ? col : 0;
            cp16(sb + OFF2_B + (uint32_t)(r * 272 + ch * 16),
                 B + (size_t)(k0 + r) * N + colc, valid);
        }
    };

    float acc[2][8][4];
#pragma unroll
    for (int mi = 0; mi < 2; mi++)
#pragma unroll
        for (int ni = 0; ni < 8; ni++)
#pragma unroll
            for (int j = 0; j < 4; j++) acc[mi][ni][j] = 0.f;

    const int NIT = K >> 6;
    load_stage(0, 0);
    cp_commit();

    const int grp = lane >> 3, w = lane & 7;
    const int a_m = (grp & 1) * 8 + w, a_k = (grp >> 1) * 8;
    const int bt_r = lane & 15, bt_c = (lane >> 4) * 8;

    for (int it = 0; it < NIT; ++it) {
        cp_wait0();
        __syncthreads();
        if (it + 1 < NIT) {
            load_stage((it + 1) & 1, (it + 1) * 64);
            cp_commit();
        }
        uint32_t sb = smb + (uint32_t)(it & 1) * STAGE2;

        uint32_t af[4][2][4];
#pragma unroll
        for (int ks = 0; ks < 4; ks++)
#pragma unroll
            for (int mi = 0; mi < 2; mi++)
                ldsm4(af[ks][mi],
                      sb + (uint32_t)((m0w + mi * 16 + a_m) * ASTR2 + ks * 16 + a_k) * 2);

#pragma unroll
        for (int ks = 0; ks < 4; ks++) {
            uint32_t bf[8][2];
#pragma unroll
            for (int nb = 0; nb < 4; nb++) {
                uint32_t t[4];
                ldsm4t(t, sb + OFF2_B +
                           (uint32_t)((ks * 16 + bt_r) * 136 + n0w + nb * 16 + bt_c) * 2);
                bf[2 * nb][0] = t[0]; bf[2 * nb][1] = t[1];
                bf[2 * nb + 1][0] = t[2]; bf[2 * nb + 1][1] = t[3];
            }
#pragma unroll
            for (int mi = 0; mi < 2; mi++)
#pragma unroll
                for (int ni = 0; ni < 8; ni++) mma_f16(acc[mi][ni], af[ks][mi], bf[ni]);
        }
    }

    __syncthreads();
    const int qr = lane >> 2, qc = (lane & 3) * 2;
#pragma unroll
    for (int mi = 0; mi < 2; mi++)
#pragma unroll
        for (int ni = 0; ni < 8; ni++) {
            int rr = row0 + m0w + mi * 16 + qr;
            int cc = col0 + n0w + ni * 8 + qc;
            if (cc < N) {
                size_t o0 = (size_t)rr * N + cc, o1 = (size_t)(rr + 8) * N + cc;
                float v0 = acc[mi][ni][0], v1 = acc[mi][ni][1];
                float v2 = acc[mi][ni][2], v3 = acc[mi][ni][3];
                if (mode == 0) {
                    if (Df) { v0 += Df[o0]; v1 += Df[o0 + 1]; v2 += Df[o1]; v3 += Df[o1 + 1]; }
                    C[o0] = v0; C[o0 + 1] = v1; C[o1] = v2; C[o1 + 1] = v3;
                } else if (mode == 1) {
                    float g0 = __half2float(Dh[o0]), g1 = __half2float(Dh[o0 + 1]);
                    float g2 = __half2float(Dh[o1]), g3 = __half2float(Dh[o1 + 1]);
                    Cs[o0] = __float2half((g0 / (1.f + __expf(-g0))) * v0);
                    Cs[o0 + 1] = __float2half((g1 / (1.f + __expf(-g1))) * v1);
                    Cs[o1] = __float2half((g2 / (1.f + __expf(-g2))) * v2);
                    Cs[o1 + 1] = __float2half((g3 / (1.f + __expf(-g3))) * v3);
                } else {
                    Cs[o0] = __float2half(v0); Cs[o0 + 1] = __float2half(v1);
                    Cs[o1] = __float2half(v2); Cs[o1 + 1] = __float2half(v3);
                }
            }
        }
}

// ==================== weight converters ====================
__global__ void wt_h1(const float4* __restrict__ W, uint2* __restrict__ Bo, int n4) {
    int stride = gridDim.x * blockDim.x;
    int i0 = blockIdx.x * blockDim.x + threadIdx.x;
    for (int i = i0; i < n4; i += stride * 4) {
        float4 v[4];
        int idx[4];
#pragma unroll
        for (int k = 0; k < 4; k++) {
            idx[k] = i + k * stride;
            if (idx[k] < n4) v[k] = W[idx[k]];
        }
#pragma unroll
        for (int k = 0; k < 4; k++) {
            if (idx[k] < n4) {
                h16 h[4];
                h[0] = __float2half(v[k].x);
                h[1] = __float2half(v[k].y);
                h[2] = __float2half(v[k].z);
                h[3] = __float2half(v[k].w);
                uint2 u;
                memcpy(&u, h, 8);
                Bo[idx[k]] = u;
            }
        }
    }
}
__global__ void wt_col(const float4* __restrict__ W, uint2* __restrict__ dst,
                       int n4, int Nsrc4, int Ndst4, int colOff4) {
    int stride = gridDim.x * blockDim.x;
    for (int i = blockIdx.x * blockDim.x + threadIdx.x; i < n4; i += stride) {
        float4 v = W[i];
        int k = i / Nsrc4, c = i - k * Nsrc4;
        h16 h[4];
        h[0] = __float2half(v.x);
        h[1] = __float2half(v.y);
        h[2] = __float2half(v.z);
        h[3] = __float2half(v.w);
        uint2 u;
        memcpy(&u, h, 8);
        dst[(size_t)k * Ndst4 + colOff4 + c] = u;
    }
}

// ==================== RMSNorm variants -> fp16 ====================
__global__ void rmsnorm_h16(const float* __restrict__ in, const float* __restrict__ w,
                            h16* __restrict__ oh, int cols, int in_ld) {
    int row = blockIdx.x;
    const float* x = in + (size_t)row * in_ld;
    float ss = 0.f;
    for (int c = threadIdx.x; c < cols; c += blockDim.x) { float v = x[c]; ss += v * v; }
    __shared__ float red[256];
    red[threadIdx.x] = ss;
    __syncthreads();
    for (int s = 128; s > 0; s >>= 1) {
        if (threadIdx.x < s) red[threadIdx.x] += red[threadIdx.x + s];
        __syncthreads();
    }
    float scale = 1.0f / sqrtf(red[0] / (float)cols + 1e-5f);
    for (int c = threadIdx.x; c < cols; c += blockDim.x) {
        float v = x[c] * scale;
        if (w) v *= w[c];
        oh[(size_t)row * cols + c] = __float2half(v);
    }
}
__global__ void rmsnorm_hh(const h16* __restrict__ in, h16* __restrict__ oh,
                           int cols, int in_ld) {
    int row = blockIdx.x;
    const h16* x = in + (size_t)row * in_ld;
    float ss = 0.f;
    for (int c = threadIdx.x; c < cols; c += blockDim.x) {
        float v = __half2float(x[c]);
        ss += v * v;
    }
    __shared__ float red[256];
    red[threadIdx.x] = ss;
    __syncthreads();
    for (int s = 128; s > 0; s >>= 1) {
        if (threadIdx.x < s) red[threadIdx.x] += red[threadIdx.x + s];
        __syncthreads();
    }
    float scale = 1.0f / sqrtf(red[0] / (float)cols + 1e-5f);
    for (int c = threadIdx.x; c < cols; c += blockDim.x)
        oh[(size_t)row * cols + c] = __float2half(__half2float(x[c]) * scale);
}

// ==================== RoPE / assemble ====================
__global__ void rope_q_kernel(const h16* __restrict__ qin, const float* __restrict__ cosT,
                              const float* __restrict__ sinT, h16* __restrict__ qout) {
    int t = blockIdx.x, h = blockIdx.y, s = t & (SEQLEN - 1);
    const float sc = 0.07216878364870323f;
    const h16* in = qin + (size_t)t * (NH * DQK) + h * DQK;
    h16* out = qout + (size_t)t * (NH * DQK) + h * DQK;
    int tid = threadIdx.x;
    if (tid < 32) {
        float xr = __half2float(in[NOPE + 2 * tid]), xi = __half2float(in[NOPE + 2 * tid + 1]);
        float c = cosT[(size_t)s * 32 + tid], sn = sinT[(size_t)s * 32 + tid];
        out[2 * tid] = __float2half((xr * c - xi * sn) * sc);
        out[2 * tid + 1] = __float2half((xr * sn + xi * c) * sc);
    }
    out[ROPE + tid] = __float2half(__half2float(in[tid]) * sc);
}

__global__ void rope_k_kernel(const h16* __restrict__ qkvl, const float* __restrict__ cosT,
                              const float* __restrict__ sinT, h16* __restrict__ krope) {
    int t = blockIdx.x, s = t & (SEQLEN - 1), j = threadIdx.x;
    const h16* in = qkvl + (size_t)t * NQKVD + QLORA + KVLORA;
    float xr = __half2float(in[2 * j]), xi = __half2float(in[2 * j + 1]);
    float c = cosT[(size_t)s * 32 + j], sn = sinT[(size_t)s * 32 + j];
    krope[(size_t)t * ROPE + 2 * j] = __float2half(xr * c - xi * sn);
    krope[(size_t)t * ROPE + 2 * j + 1] = __float2half(xr * sn + xi * c);
}

__global__ void assemble_kv(const h16* __restrict__ krope, const h16* __restrict__ kv,
                            h16* __restrict__ K, h16* __restrict__ V) {
    int t = blockIdx.x, h = blockIdx.y, d = threadIdx.x;
    if (d < DQK) {
        h16 v = (d < ROPE) ? krope[(size_t)t * ROPE + d]
                           : kv[(size_t)t * (NH * (NOPE + DV)) + h * NOPE + (d - ROPE)];
        K[(size_t)t * (NH * DQK) + h * DQK + d] = v;
    } else {
        int c = d - DQK;
        V[(size_t)t * (NH * DV) + h * DV + c] =
            kv[(size_t)t * (NH * (NOPE + DV)) + NH * NOPE + h * DV + c];
    }
}

// ==================== fp16 HMMA flash attention: Q-tile 128, 2-stage K/V ====================
#define QKSTR 200
#define VSTR 136
#define AQ_BYTES (128 * QKSTR * 2)          // 51200
#define KSTG (64 * QKSTR * 2)               // 25600
#define VSTG (64 * VSTR * 2)                // 17408
#define MSTG 256
#define KVSTAGE (KSTG + VSTG + MSTG)        // 43264
#define ATT_SMEM2 (AQ_BYTES + 2 * KVSTAGE)  // 137728

__global__ __launch_bounds__(256) void attn_mma(
    const h16* __restrict__ Q, const h16* __restrict__ K, const h16* __restrict__ V,
    const int* __restrict__ seqmask, h16* __restrict__ O) {
    extern __shared__ __align__(128) char smc[];
    const int tid = threadIdx.x, wid = tid >> 5, lane = tid & 31;
    const int qblk = gridDim.x - 1 - blockIdx.x;  // longest first
    const int h = blockIdx.y, b = blockIdx.z;
    const int warpm = wid * 16;
    const uint32_t smb = smem_u32(smc);
    const uint32_t qsb = smb;

    auto ksb = [&](int s) { return smb + AQ_BYTES + (uint32_t)s * KVSTAGE; };
    auto vsb = [&](int s) { return smb + AQ_BYTES + (uint32_t)s * KVSTAGE + KSTG; };
    auto mskp = [&](int s) { return (float*)(smc + AQ_BYTES + s * KVSTAGE + KSTG + VSTG); };

    // load Q (128 x 192)
    {
        const h16* Qg = Q + ((size_t)(b * SEQLEN + qblk * 128) * NH + h) * DQK;
#pragma unroll
        for (int p = 0; p < 12; p++) {
            int idx = tid + p * 256;
            int r = idx / 24, ch = idx % 24;
            cp16(qsb + (uint32_t)(r * QKSTR + ch * 8) * 2, Qg + (size_t)r * (NH * DQK) + ch * 8, 16);
        }
        cp_commit();
        cp_wait0();
    }
    __syncthreads();

    const int grp = lane >> 3, w = lane & 7;
    const int a_m = (grp & 1) * 8 + w, a_k = (grp >> 1) * 8;
    const int b_n = (grp >> 1) * 8 + w, b_k = (grp & 1) * 8;

    uint32_t qf[12][4];
#pragma unroll
    for (int kc = 0; kc < 12; kc++)
        ldsm4(qf[kc], qsb + (uint32_t)((warpm + a_m) * QKSTR + kc * 16 + a_k) * 2);

    float acc[16][4];
#pragma unroll
    for (int i = 0; i < 16; i++)
#pragma unroll
        for (int j = 0; j < 4; j++) acc[i][j] = 0.f;
    float m0 = -1e30f, m1 = -1e30f, l0 = 0.f, l1 = 0.f;
    const int srow0 = qblk * 128 + warpm + (lane >> 2);  // global seq row
    const int srow1 = srow0 + 8;

    const int ktmax = 2 * qblk + 2;

    auto load_kv = [&](int s, int kt) {
        const h16* Kg = K + ((size_t)(b * SEQLEN + kt * 64) * NH + h) * DQK;
        uint32_t kb = ksb(s);
#pragma unroll
        for (int p = 0; p < 6; p++) {
            int idx = tid + p * 256;
            int r = idx / 24, ch = idx % 24;
            cp16(kb + (uint32_t)(r * QKSTR + ch * 8) * 2, Kg + (size_t)r * (NH * DQK) + ch * 8, 16);
        }
        const h16* Vg = V + (size_t)(b * SEQLEN + kt * 64) * (NH * DV) + h * DV;
        uint32_t vb = vsb(s);
#pragma unroll
        for (int p = 0; p < 4; p++) {
            int idx = tid + p * 256;
            int r = idx >> 4, ch = idx & 15;
            cp16(vb + (uint32_t)(r * VSTR + ch * 8) * 2, Vg + (size_t)r * (NH * DV) + ch * 8, 16);
        }
        if (tid < 64)
            mskp(s)[tid] = (seqmask[b * SEQLEN + kt * 64 + tid] > 0) ? 0.f : -1e30f;
    };

    load_kv(0, 0);
    cp_commit();

    for (int kt = 0; kt < ktmax; kt++) {
        if (kt + 1 < ktmax) {
            load_kv((kt + 1) & 1, kt + 1);
            cp_commit();
            cp_wait1();
        } else {
            cp_wait0();
        }
        __syncthreads();
        int st = kt & 1;
        uint32_t kb = ksb(st), vb = vsb(st);
        float* maskf = mskp(st);

        float s[8][4];
#pragma unroll
        for (int nt = 0; nt < 8; nt++)
#pragma unroll
            for (int j = 0; j < 4; j++) s[nt][j] = 0.f;
#pragma unroll
        for (int kc = 0; kc < 12; kc++)
#pragma unroll
            for (int nb = 0; nb < 4; nb++) {
                uint32_t t[4];
                ldsm4(t, kb + (uint32_t)((nb * 16 + b_n) * QKSTR + kc * 16 + b_k) * 2);
                uint32_t bf0[2] = {t[0], t[1]}, bf1[2] = {t[2], t[3]};
                mma_f16(s[2 * nb], qf[kc], bf0);
                mma_f16(s[2 * nb + 1], qf[kc], bf1);
            }
        bool dg0 = (kt * 64 + 63) > srow0;
        bool dg1 = (kt * 64 + 63) > srow1;
#pragma unroll
        for (int nt = 0; nt < 8; nt++) {
            int c0 = nt * 8 + (lane & 3) * 2;
            int cg = kt * 64 + c0;
            float ma0 = maskf[c0], ma1 = maskf[c0 + 1];
            s[nt][0] += ma0; s[nt][1] += ma1; s[nt][2] += ma0; s[nt][3] += ma1;
            if (dg0) {
                if (cg > srow0) s[nt][0] = -1e30f;
                if (cg + 1 > srow0) s[nt][1] = -1e30f;
            }
            if (dg1) {
                if (cg > srow1) s[nt][2] = -1e30f;
                if (cg + 1 > srow1) s[nt][3] = -1e30f;
            }
        }
        float mx0 = -1e30f, mx1 = -1e30f;
#pragma unroll
        for (int nt = 0; nt < 8; nt++) {
            mx0 = fmaxf(mx0, fmaxf(s[nt][0], s[nt][1]));
            mx1 = fmaxf(mx1, fmaxf(s[nt][2], s[nt][3]));
        }
        mx0 = fmaxf(mx0, __shfl_xor_sync(0xffffffff, mx0, 1));
        mx0 = fmaxf(mx0, __shfl_xor_sync(0xffffffff, mx0, 2));
        mx1 = fmaxf(mx1, __shfl_xor_sync(0xffffffff, mx1, 1));
        mx1 = fmaxf(mx1, __shfl_xor_sync(0xffffffff, mx1, 2));
        float mn0 = fmaxf(m0, mx0), mn1 = fmaxf(m1, mx1);
        float cr0 = __expf(m0 - mn0), cr1 = __expf(m1 - mn1);
        float sum0 = 0.f, sum1 = 0.f;
#pragma unroll
        for (int nt = 0; nt < 8; nt++) {
            s[nt][0] = __expf(s[nt][0] - mn0);
            s[nt][1] = __expf(s[nt][1] - mn0);
            s[nt][2] = __expf(s[nt][2] - mn1);
            s[nt][3] = __expf(s[nt][3] - mn1);
            sum0 += s[nt][0] + s[nt][1];
            sum1 += s[nt][2] + s[nt][3];
        }
        sum0 += __shfl_xor_sync(0xffffffff, sum0, 1);
        sum0 += __shfl_xor_sync(0xffffffff, sum0, 2);
        sum1 += __shfl_xor_sync(0xffffffff, sum1, 1);
        sum1 += __shfl_xor_sync(0xffffffff, sum1, 2);
        l0 = l0 * cr0 + sum0;
        l1 = l1 * cr1 + sum1;
        m0 = mn0; m1 = mn1;
#pragma unroll
        for (int i = 0; i < 16; i++) {
            acc[i][0] *= cr0; acc[i][1] *= cr0;
            acc[i][2] *= cr1; acc[i][3] *= cr1;
        }
        uint32_t pf[4][4];
#pragma unroll
        for (int kc = 0; kc < 4; kc++) {
            int j0 = 2 * kc;
            pf[kc][0] = pack2h(s[j0][0], s[j0][1]);
            pf[kc][1] = pack2h(s[j0][2], s[j0][3]);
            pf[kc][2] = pack2h(s[j0 + 1][0], s[j0 + 1][1]);
            pf[kc][3] = pack2h(s[j0 + 1][2], s[j0 + 1][3]);
        }
#pragma unroll
        for (int kc = 0; kc < 4; kc++)
#pragma unroll
            for (int np = 0; np < 8; np++) {
                uint32_t t[4];
                uint32_t addr = vb + (uint32_t)((kc * 16 + (lane & 15)) * VSTR + np * 16 + (lane >> 4) * 8) * 2;
                ldsm4t(t, addr);
                uint32_t bf0[2] = {t[0], t[1]}, bf1[2] = {t[2], t[3]};
                mma_f16(acc[2 * np], pf[kc], bf0);
                mma_f16(acc[2 * np + 1], pf[kc], bf1);
            }
        __syncthreads();
    }

    float inv0 = 1.f / l0, inv1 = 1.f / l1;
    int r0g = b * SEQLEN + srow0;
#pragma unroll
    for (int nt = 0; nt < 16; nt++) {
        int cc = nt * 8 + (lane & 3) * 2;
        size_t o0 = (size_t)r0g * (NH * DV) + h * DV + cc;
        size_t o1 = o0 + 8 * (size_t)(NH * DV);
        O[o0] = __float2half(acc[nt][0] * inv0);
        O[o0 + 1] = __float2half(acc[nt][1] * inv0);
        O[o1] = __float2half(acc[nt][2] * inv1);
        O[o1 + 1] = __float2half(acc[nt][3] * inv1);
    }
}

// ==================== launch ====================
extern "C" void kernel_launch(void* const* d_in, const int* in_sizes, int n_in,
                              void* d_out, int out_size) {
    const float* hidden = (const float*)d_in[0];
    const int* seqmask = (const int*)d_in[1];
    const float* cosT = (const float*)d_in[2];
    const float* sinT = (const float*)d_in[3];
    const float* ln1 = (const float*)d_in[4];
    const float* ln2 = (const float*)d_in[5];
    const float* Wq_down = (const float*)d_in[6];
    const float* Wq_up = (const float*)d_in[7];
    const float* Wkv_down = (const float*)d_in[8];
    const float* Wkv_up = (const float*)d_in[9];
    const float* Wo = (const float*)d_in[10];
    const float* Wgate = (const float*)d_in[11];
    const float* Wup = (const float*)d_in[12];
    const float* Wdown = (const float*)d_in[13];
    float* out = (float*)d_out;

#define SYM(p, s) cudaGetSymbolAddress((void**)&p, s)
    float* p_x;
    SYM(p_x, g_x);
    h16 *hf, *qkvl, *qlnf, *kvnf, *qh, *kvh, *krope, *h2, *gateh, *ff;
    h16 *Qf, *Kf, *Vf, *atf;
    SYM(hf, g_hf); SYM(qkvl, g_qkvl); SYM(qlnf, g_qlnf); SYM(kvnf, g_kvnf);
    SYM(qh, g_qh); SYM(kvh, g_kvh); SYM(krope, g_krope); SYM(h2, g_h2);
    SYM(gateh, g_gateh); SYM(ff, g_ff);
    SYM(Qf, g_Qf); SYM(Kf, g_Kf); SYM(Vf, g_Vf); SYM(atf, g_atf);
    h16 *wqkvd, *wqu, *wkvu, *wo, *wg, *wu, *wd;
    SYM(wqkvd, g_wqkvd); SYM(wqu, g_wqu); SYM(wkvu, g_wkvu); SYM(wo, g_wo);
    SYM(wg, g_wg); SYM(wu, g_wu); SYM(wd, g_wd);
#undef SYM

    cudaFuncSetAttribute(h1gemm, cudaFuncAttributeMaxDynamicSharedMemorySize, GEMM_SMEM2);
    cudaFuncSetAttribute(attn_mma, cudaFuncAttributeMaxDynamicSharedMemorySize, ATT_SMEM2);

    wt_col<<<2048, 256>>>((const float4*)Wq_down, (uint2*)wqkvd,
                          DM * QLORA / 4, QLORA / 4, NQKVD / 4, 0);
    wt_col<<<2048, 256>>>((const float4*)Wkv_down, (uint2*)wqkvd,
                          DM * (KVLORA + ROPE) / 4, (KVLORA + ROPE) / 4, NQKVD / 4, QLORA / 4);
    rmsnorm_h16<<<TOKENS, 256>>>(hidden, ln1, hf, DM, DM);

    h1gemm<<<dim3((NQKVD + 127) / 128, TOKENS / 128), 256, GEMM_SMEM2>>>(
        hf, wqkvd, nullptr, nullptr, nullptr, qkvl, 2, TOKENS, NQKVD, DM);

    wt_h1<<<1024, 256>>>((const float4*)Wq_up, (uint2*)wqu, QLORA * NH * DQK / 4);
    rmsnorm_hh<<<TOKENS, 256>>>(qkvl, qlnf, QLORA, NQKVD);
    h1gemm<<<dim3((NH * DQK) / 128, TOKENS / 128), 256, GEMM_SMEM2>>>(
        qlnf, wqu, nullptr, nullptr, nullptr, qh, 2, TOKENS, NH * DQK, QLORA);
    rope_q_kernel<<<dim3(TOKENS, NH), 128>>>(qh, cosT, sinT, Qf);

    rope_k_kernel<<<TOKENS, 32>>>(qkvl, cosT, sinT, krope);
    rmsnorm_hh<<<TOKENS, 256>>>(qkvl + QLORA, kvnf, KVLORA, NQKVD);

    wt_h1<<<1024, 256>>>((const float4*)Wkv_up, (uint2*)wkvu, KVLORA * NH * (NOPE + DV) / 4);
    h1gemm<<<dim3((NH * (NOPE + DV)) / 128, TOKENS / 128), 256, GEMM_SMEM2>>>(
        kvnf, wkvu, nullptr, nullptr, nullptr, kvh, 2, TOKENS, NH * (NOPE + DV), KVLORA);
    assemble_kv<<<dim3(TOKENS, NH), DQK + DV>>>(krope, kvh, Kf, Vf);

    wt_h1<<<1024, 256>>>((const float4*)Wo, (uint2*)wo, NH * DV * DM / 4);
    wt_h1<<<1024, 256>>>((const float4*)Wgate, (uint2*)wg, DM * DFF / 4);
    wt_h1<<<1024, 256>>>((const float4*)Wup, (uint2*)wu, DM * DFF / 4);
    wt_h1<<<1024, 256>>>((const float4*)Wdown, (uint2*)wd, DFF * DM / 4);

    attn_mma<<<dim3(SEQLEN / 128, NH, NB), 256, ATT_SMEM2>>>(Qf, Kf, Vf, seqmask, atf);

    h1gemm<<<dim3(DM / 128, TOKENS / 128), 256, GEMM_SMEM2>>>(
        atf, wo, hidden, nullptr, p_x, nullptr, 0, TOKENS, DM, NH * DV);

    rmsnorm_h16<<<TOKENS, 256>>>(p_x, ln2, h2, DM, DM);

    h1gemm<<<dim3(DFF / 128, TOKENS / 128), 256, GEMM_SMEM2>>>(
        h2, wg, nullptr, nullptr, nullptr, gateh, 2, TOKENS, DFF, DM);
    h1gemm<<<dim3(DFF / 128, TOKENS / 128), 256, GEMM_SMEM2>>>(
        h2, wu, nullptr, gateh, nullptr, ff, 1, TOKENS, DFF, DM);

    h1gemm<<<dim3(DM / 128, TOKENS / 128), 256, GEMM_SMEM2>>>(
        ff, wd, p_x, nullptr, out, nullptr, 0, TOKENS, DM, DFF);
}

// round 14
// speedup vs baseline: 1.0667x; 1.0667x over previous
#include <cuda_runtime.h>
#include <cuda_fp16.h>
#include <math.h>
#include <string.h>
#include <stdint.h>

#define TOKENS 4096
#define SEQLEN 2048
#define NB 2
#define DM 2048
#define NH 16
#define QLORA 1536
#define KVLORA 512
#define NOPE 128
#define ROPE 64
#define DQK 192
#define DV 128
#define DFF 8192
#define NQKVD (QLORA + KVLORA + ROPE)   // 2112

typedef __half h16;

// fp32 scratch (residual stream only)
__device__ float g_x[TOKENS * DM];
// fp16 activations
__device__ h16 g_hf[TOKENS * DM];
__device__ h16 g_qkvl[TOKENS * NQKVD];
__device__ h16 g_qlnf[TOKENS * QLORA];
__device__ h16 g_kvnf[TOKENS * KVLORA];
__device__ h16 g_qh[TOKENS * NH * DQK];
__device__ h16 g_kvh[TOKENS * NH * (NOPE + DV)];
__device__ h16 g_krope[TOKENS * ROPE];
__device__ h16 g_h2[TOKENS * DM];
__device__ h16 g_ff[TOKENS * DFF];
__device__ h16 g_Qf[TOKENS * NH * DQK];
__device__ h16 g_Kf[TOKENS * NH * DQK];
__device__ h16 g_Vf[TOKENS * NH * DV];
__device__ h16 g_atf[TOKENS * NH * DV];
// fp16 weights [K][N]
__device__ h16 g_wqkvd[DM * NQKVD];
__device__ h16 g_wqu[QLORA * (NH * DQK)];
__device__ h16 g_wkvu[KVLORA * (NH * (NOPE + DV))];
__device__ h16 g_wo[(NH * DV) * DM];
__device__ h16 g_wgu[DM * (2 * DFF)];   // interleaved gate/up columns
__device__ h16 g_wd[DFF * DM];

// ==================== PTX helpers ====================
__device__ __forceinline__ uint32_t smem_u32(const void* p) {
    uint32_t a;
    asm("{ .reg .u64 t; cvta.to.shared.u64 t, %1; cvt.u32.u64 %0, t; }" : "=r"(a) : "l"(p));
    return a;
}
__device__ __forceinline__ void cp16(uint32_t d, const void* s, int sz) {
    asm volatile("cp.async.cg.shared.global [%0], [%1], 16, %2;" :: "r"(d), "l"(s), "r"(sz) : "memory");
}
__device__ __forceinline__ void cp_commit() { asm volatile("cp.async.commit_group;" ::: "memory"); }
__device__ __forceinline__ void cp_wait0() { asm volatile("cp.async.wait_group 0;" ::: "memory"); }
__device__ __forceinline__ void cp_wait1() { asm volatile("cp.async.wait_group 1;" ::: "memory"); }
__device__ __forceinline__ void ldsm4(uint32_t* r, uint32_t a) {
    asm volatile("ldmatrix.sync.aligned.m8n8.x4.shared.b16 {%0, %1, %2, %3}, [%4];"
                 : "=r"(r[0]), "=r"(r[1]), "=r"(r[2]), "=r"(r[3]) : "r"(a));
}
__device__ __forceinline__ void ldsm4t(uint32_t* r, uint32_t a) {
    asm volatile("ldmatrix.sync.aligned.m8n8.x4.trans.shared.b16 {%0, %1, %2, %3}, [%4];"
                 : "=r"(r[0]), "=r"(r[1]), "=r"(r[2]), "=r"(r[3]) : "r"(a));
}
__device__ __forceinline__ void mma_f16(float* c, const uint32_t* a, const uint32_t* b) {
    asm volatile(
        "mma.sync.aligned.m16n8k16.row.col.f32.f16.f16.f32 "
        "{%0, %1, %2, %3}, {%4, %5, %6, %7}, {%8, %9}, {%0, %1, %2, %3};"
        : "+f"(c[0]), "+f"(c[1]), "+f"(c[2]), "+f"(c[3])
        : "r"(a[0]), "r"(a[1]), "r"(a[2]), "r"(a[3]), "r"(b[0]), "r"(b[1]));
}
__device__ __forceinline__ uint32_t pack2h(float a, float b) {
    __half2 h = __floats2half2_rn(a, b);
    uint32_t u;
    memcpy(&u, &h, 4);
    return u;
}

// ==================== GEMM tiling: BK=64, 2 stages, 2 CTA/SM (round-12 proven) ====================
#define ASTR2 72
#define A2_BYTES (128 * ASTR2 * 2)
#define B2_BYTES (64 * 136 * 2)
#define OFF2_B A2_BYTES
#define STAGE2 (A2_BYTES + B2_BYTES)
#define GEMM_SMEM2 (2 * STAGE2)

// mode 0: C(fp32) = acc (+Df)
// mode 2: Cs(fp16) = acc
// mode 3: interleaved gate/up: Cs[rr][cc/2] = silu(v_even) * v_odd  (out stride N/2)
__global__ __launch_bounds__(256, 2) void h1gemm(
    const h16* __restrict__ A, const h16* __restrict__ B,
    const float* __restrict__ Df,
    float* __restrict__ C, h16* __restrict__ Cs,
    int mode, int M, int N, int K) {
    extern __shared__ __align__(128) char sm[];
    const int tid = threadIdx.x, wid = tid >> 5, lane = tid & 31;
    const int row0 = blockIdx.y * 128, col0 = blockIdx.x * 128;
    const int m0w = (wid >> 1) * 32, n0w = (wid & 1) * 64;
    const uint32_t smb = smem_u32(sm);

    auto load_stage = [&](int s, int k0) {
        uint32_t sb = smb + (uint32_t)s * STAGE2;
#pragma unroll
        for (int p = 0; p < 4; p++) {
            int idx = tid + p * 256;
            int r = idx >> 3, ch = idx & 7;
            cp16(sb + (uint32_t)(r * 144 + ch * 16),
                 A + (size_t)(row0 + r) * K + k0 + ch * 8, 16);
        }
#pragma unroll
        for (int p = 0; p < 4; p++) {
            int idx = tid + p * 256;
            int r = idx >> 4, ch = idx & 15;
            int col = col0 + ch * 8;
            int valid = (col < N) ? 16 : 0;
            int colc = (col < N) ? col : 0;
            cp16(sb + OFF2_B + (uint32_t)(r * 272 + ch * 16),
                 B + (size_t)(k0 + r) * N + colc, valid);
        }
    };

    float acc[2][8][4];
#pragma unroll
    for (int mi = 0; mi < 2; mi++)
#pragma unroll
        for (int ni = 0; ni < 8; ni++)
#pragma unroll
            for (int j = 0; j < 4; j++) acc[mi][ni][j] = 0.f;

    const int NIT = K >> 6;
    load_stage(0, 0);
    cp_commit();

    const int grp = lane >> 3, w = lane & 7;
    const int a_m = (grp & 1) * 8 + w, a_k = (grp >> 1) * 8;
    const int bt_r = lane & 15, bt_c = (lane >> 4) * 8;

    for (int it = 0; it < NIT; ++it) {
        cp_wait0();
        __syncthreads();
        if (it + 1 < NIT) {
            load_stage((it + 1) & 1, (it + 1) * 64);
            cp_commit();
        }
        uint32_t sb = smb + (uint32_t)(it & 1) * STAGE2;

        uint32_t af[4][2][4];
#pragma unroll
        for (int ks = 0; ks < 4; ks++)
#pragma unroll
            for (int mi = 0; mi < 2; mi++)
                ldsm4(af[ks][mi],
                      sb + (uint32_t)((m0w + mi * 16 + a_m) * ASTR2 + ks * 16 + a_k) * 2);

#pragma unroll
        for (int ks = 0; ks < 4; ks++) {
            uint32_t bf[8][2];
#pragma unroll
            for (int nb = 0; nb < 4; nb++) {
                uint32_t t[4];
                ldsm4t(t, sb + OFF2_B +
                           (uint32_t)((ks * 16 + bt_r) * 136 + n0w + nb * 16 + bt_c) * 2);
                bf[2 * nb][0] = t[0]; bf[2 * nb][1] = t[1];
                bf[2 * nb + 1][0] = t[2]; bf[2 * nb + 1][1] = t[3];
            }
#pragma unroll
            for (int mi = 0; mi < 2; mi++)
#pragma unroll
                for (int ni = 0; ni < 8; ni++) mma_f16(acc[mi][ni], af[ks][mi], bf[ni]);
        }
    }

    __syncthreads();
    const int qr = lane >> 2, qc = (lane & 3) * 2;
#pragma unroll
    for (int mi = 0; mi < 2; mi++)
#pragma unroll
        for (int ni = 0; ni < 8; ni++) {
            int rr = row0 + m0w + mi * 16 + qr;
            int cc = col0 + n0w + ni * 8 + qc;
            if (cc < N) {
                float v0 = acc[mi][ni][0], v1 = acc[mi][ni][1];
                float v2 = acc[mi][ni][2], v3 = acc[mi][ni][3];
                if (mode == 0) {
                    size_t o0 = (size_t)rr * N + cc, o1 = (size_t)(rr + 8) * N + cc;
                    if (Df) { v0 += Df[o0]; v1 += Df[o0 + 1]; v2 += Df[o1]; v3 += Df[o1 + 1]; }
                    C[o0] = v0; C[o0 + 1] = v1; C[o1] = v2; C[o1 + 1] = v3;
                } else if (mode == 2) {
                    size_t o0 = (size_t)rr * N + cc, o1 = (size_t)(rr + 8) * N + cc;
                    Cs[o0] = __float2half(v0); Cs[o0 + 1] = __float2half(v1);
                    Cs[o1] = __float2half(v2); Cs[o1 + 1] = __float2half(v3);
                } else {
                    // mode 3: (v0,v1)=(gate,up) at out col cc/2, stride N/2
                    int half_n = N >> 1;
                    size_t o0 = (size_t)rr * half_n + (cc >> 1);
                    size_t o1 = (size_t)(rr + 8) * half_n + (cc >> 1);
                    Cs[o0] = __float2half((v0 / (1.f + __expf(-v0))) * v1);
                    Cs[o1] = __float2half((v2 / (1.f + __expf(-v2))) * v3);
                }
            }
        }
}

// ==================== weight converters ====================
__global__ void wt_h1(const float4* __restrict__ W, uint2* __restrict__ Bo, int n4) {
    int stride = gridDim.x * blockDim.x;
    int i0 = blockIdx.x * blockDim.x + threadIdx.x;
    for (int i = i0; i < n4; i += stride * 4) {
        float4 v[4];
        int idx[4];
#pragma unroll
        for (int k = 0; k < 4; k++) {
            idx[k] = i + k * stride;
            if (idx[k] < n4) v[k] = W[idx[k]];
        }
#pragma unroll
        for (int k = 0; k < 4; k++) {
            if (idx[k] < n4) {
                h16 h[4];
                h[0] = __float2half(v[k].x);
                h[1] = __float2half(v[k].y);
                h[2] = __float2half(v[k].z);
                h[3] = __float2half(v[k].w);
                uint2 u;
                memcpy(&u, h, 8);
                Bo[idx[k]] = u;
            }
        }
    }
}
__global__ void wt_col(const float4* __restrict__ W, uint2* __restrict__ dst,
                       int n4, int Nsrc4, int Ndst4, int colOff4) {
    int stride = gridDim.x * blockDim.x;
    for (int i = blockIdx.x * blockDim.x + threadIdx.x; i < n4; i += stride) {
        float4 v = W[i];
        int k = i / Nsrc4, c = i - k * Nsrc4;
        h16 h[4];
        h[0] = __float2half(v.x);
        h[1] = __float2half(v.y);
        h[2] = __float2half(v.z);
        h[3] = __float2half(v.w);
        uint2 u;
        memcpy(&u, h, 8);
        dst[(size_t)k * Ndst4 + colOff4 + c] = u;
    }
}
// interleave gate/up columns: dst[k][2j]=g[k][j], dst[k][2j+1]=u[k][j]
__global__ void wt_gu(const float4* __restrict__ Wg, const float4* __restrict__ Wu,
                      uint4* __restrict__ dst, int n4) {   // n4 = DM*DFF/4
    int stride = gridDim.x * blockDim.x;
    for (int i = blockIdx.x * blockDim.x + threadIdx.x; i < n4; i += stride) {
        float4 g = Wg[i], u = Wu[i];
        h16 h[8];
        h[0] = __float2half(g.x); h[1] = __float2half(u.x);
        h[2] = __float2half(g.y); h[3] = __float2half(u.y);
        h[4] = __float2half(g.z); h[5] = __float2half(u.z);
        h[6] = __float2half(g.w); h[7] = __float2half(u.w);
        uint4 o;
        memcpy(&o, h, 16);
        dst[i] = o;   // row k, out cols [8t..8t+7] where i = k*(DFF/4)+t
    }
}

// ==================== RMSNorm variants -> fp16 ====================
__global__ void rmsnorm_h16(const float* __restrict__ in, const float* __restrict__ w,
                            h16* __restrict__ oh, int cols, int in_ld) {
    int row = blockIdx.x;
    const float* x = in + (size_t)row * in_ld;
    float ss = 0.f;
    for (int c = threadIdx.x; c < cols; c += blockDim.x) { float v = x[c]; ss += v * v; }
    __shared__ float red[256];
    red[threadIdx.x] = ss;
    __syncthreads();
    for (int s = 128; s > 0; s >>= 1) {
        if (threadIdx.x < s) red[threadIdx.x] += red[threadIdx.x + s];
        __syncthreads();
    }
    float scale = 1.0f / sqrtf(red[0] / (float)cols + 1e-5f);
    for (int c = threadIdx.x; c < cols; c += blockDim.x) {
        float v = x[c] * scale;
        if (w) v *= w[c];
        oh[(size_t)row * cols + c] = __float2half(v);
    }
}
__global__ void rmsnorm_hh(const h16* __restrict__ in, h16* __restrict__ oh,
                           int cols, int in_ld) {
    int row = blockIdx.x;
    const h16* x = in + (size_t)row * in_ld;
    float ss = 0.f;
    for (int c = threadIdx.x; c < cols; c += blockDim.x) {
        float v = __half2float(x[c]);
        ss += v * v;
    }
    __shared__ float red[256];
    red[threadIdx.x] = ss;
    __syncthreads();
    for (int s = 128; s > 0; s >>= 1) {
        if (threadIdx.x < s) red[threadIdx.x] += red[threadIdx.x + s];
        __syncthreads();
    }
    float scale = 1.0f / sqrtf(red[0] / (float)cols + 1e-5f);
    for (int c = threadIdx.x; c < cols; c += blockDim.x)
        oh[(size_t)row * cols + c] = __float2half(__half2float(x[c]) * scale);
}

// ==================== RoPE / assemble ====================
__global__ void rope_q_kernel(const h16* __restrict__ qin, const float* __restrict__ cosT,
                              const float* __restrict__ sinT, h16* __restrict__ qout) {
    int t = blockIdx.x, h = blockIdx.y, s = t & (SEQLEN - 1);
    const float sc = 0.07216878364870323f;
    const h16* in = qin + (size_t)t * (NH * DQK) + h * DQK;
    h16* out = qout + (size_t)t * (NH * DQK) + h * DQK;
    int tid = threadIdx.x;
    if (tid < 32) {
        float xr = __half2float(in[NOPE + 2 * tid]), xi = __half2float(in[NOPE + 2 * tid + 1]);
        float c = cosT[(size_t)s * 32 + tid], sn = sinT[(size_t)s * 32 + tid];
        out[2 * tid] = __float2half((xr * c - xi * sn) * sc);
        out[2 * tid + 1] = __float2half((xr * sn + xi * c) * sc);
    }
    out[ROPE + tid] = __float2half(__half2float(in[tid]) * sc);
}

__global__ void rope_k_kernel(const h16* __restrict__ qkvl, const float* __restrict__ cosT,
                              const float* __restrict__ sinT, h16* __restrict__ krope) {
    int t = blockIdx.x, s = t & (SEQLEN - 1), j = threadIdx.x;
    const h16* in = qkvl + (size_t)t * NQKVD + QLORA + KVLORA;
    float xr = __half2float(in[2 * j]), xi = __half2float(in[2 * j + 1]);
    float c = cosT[(size_t)s * 32 + j], sn = sinT[(size_t)s * 32 + j];
    krope[(size_t)t * ROPE + 2 * j] = __float2half(xr * c - xi * sn);
    krope[(size_t)t * ROPE + 2 * j + 1] = __float2half(xr * sn + xi * c);
}

__global__ void assemble_kv(const h16* __restrict__ krope, const h16* __restrict__ kv,
                            h16* __restrict__ K, h16* __restrict__ V) {
    int t = blockIdx.x, h = blockIdx.y, d = threadIdx.x;
    if (d < DQK) {
        h16 v = (d < ROPE) ? krope[(size_t)t * ROPE + d]
                           : kv[(size_t)t * (NH * (NOPE + DV)) + h * NOPE + (d - ROPE)];
        K[(size_t)t * (NH * DQK) + h * DQK + d] = v;
    } else {
        int c = d - DQK;
        V[(size_t)t * (NH * DV) + h * DV + c] =
            kv[(size_t)t * (NH * (NOPE + DV)) + NH * NOPE + h * DV + c];
    }
}

// ==================== fp16 HMMA flash attention (round-12 proven, 64-row tile) ====================
#define QKSTR 200
#define VSTR 136
#define ATT_SMEM ((64 * QKSTR * 2 + 64 * VSTR) * 2 + 64 * 4)

__global__ __launch_bounds__(128) void attn_mma(
    const h16* __restrict__ Q, const h16* __restrict__ K, const h16* __restrict__ V,
    const int* __restrict__ seqmask, h16* __restrict__ O) {
    extern __shared__ __align__(128) char smc[];
    const int tid = threadIdx.x, wid = tid >> 5, lane = tid & 31;
    const int qt = gridDim.x - 1 - blockIdx.x, h = blockIdx.y, b = blockIdx.z;
    const int warpm = wid * 16;
    const uint32_t smb = smem_u32(smc);
    const uint32_t qsb = smb, ksb = smb + 64 * QKSTR * 2, vsb = ksb + 64 * QKSTR * 2;
    float* maskf = (float*)(smc + 64 * QKSTR * 4 + 64 * VSTR * 2);

    {
        const h16* Qg = Q + ((size_t)(b * SEQLEN + qt * 64) * NH + h) * DQK;
#pragma unroll
        for (int p = 0; p < 12; p++) {
            int idx = tid + p * 128;
            int r = idx / 24, ch = idx % 24;
            cp16(qsb + (uint32_t)(r * QKSTR + ch * 8) * 2, Qg + (size_t)r * (NH * DQK) + ch * 8, 16);
        }
        cp_commit();
        cp_wait0();
    }
    __syncthreads();

    const int grp = lane >> 3, w = lane & 7;
    const int a_m = (grp & 1) * 8 + w, a_k = (grp >> 1) * 8;
    const int b_n = (grp >> 1) * 8 + w, b_k = (grp & 1) * 8;

    uint32_t qf[12][4];
#pragma unroll
    for (int kc = 0; kc < 12; kc++)
        ldsm4(qf[kc], qsb + (uint32_t)((warpm + a_m) * QKSTR + kc * 16 + a_k) * 2);

    float acc[16][4];
#pragma unroll
    for (int i = 0; i < 16; i++)
#pragma unroll
        for (int j = 0; j < 4; j++) acc[i][j] = 0.f;
    float m0 = -1e30f, m1 = -1e30f, l0 = 0.f, l1 = 0.f;
    const int rloc0 = warpm + (lane >> 2), rloc1 = rloc0 + 8;

    for (int kt = 0; kt <= qt; kt++) {
        __syncthreads();
        {
            const h16* Kg = K + ((size_t)(b * SEQLEN + kt * 64) * NH + h) * DQK;
#pragma unroll
            for (int p = 0; p < 12; p++) {
                int idx = tid + p * 128;
                int r = idx / 24, ch = idx % 24;
                cp16(ksb + (uint32_t)(r * QKSTR + ch * 8) * 2, Kg + (size_t)r * (NH * DQK) + ch * 8, 16);
            }
            const h16* Vg = V + (size_t)(b * SEQLEN + kt * 64) * (NH * DV) + h * DV;
#pragma unroll
            for (int p = 0; p < 8; p++) {
                int idx = tid + p * 128;
                int r = idx >> 4, ch = idx & 15;
                cp16(vsb + (uint32_t)(r * VSTR + ch * 8) * 2, Vg + (size_t)r * (NH * DV) + ch * 8, 16);
            }
            if (tid < 64)
                maskf[tid] = (seqmask[b * SEQLEN + kt * 64 + tid] > 0) ? 0.f : -1e30f;
            cp_commit();
            cp_wait0();
        }
        __syncthreads();

        float s[8][4];
#pragma unroll
        for (int nt = 0; nt < 8; nt++)
#pragma unroll
            for (int j = 0; j < 4; j++) s[nt][j] = 0.f;
#pragma unroll
        for (int kc = 0; kc < 12; kc++)
#pragma unroll
            for (int nb = 0; nb < 4; nb++) {
                uint32_t t[4];
                ldsm4(t, ksb + (uint32_t)((nb * 16 + b_n) * QKSTR + kc * 16 + b_k) * 2);
                uint32_t bf0[2] = {t[0], t[1]}, bf1[2] = {t[2], t[3]};
                mma_f16(s[2 * nb], qf[kc], bf0);
                mma_f16(s[2 * nb + 1], qf[kc], bf1);
            }
        bool diag = (kt == qt);
#pragma unroll
        for (int nt = 0; nt < 8; nt++) {
            int c0 = nt * 8 + (lane & 3) * 2;
            float ma0 = maskf[c0], ma1 = maskf[c0 + 1];
            s[nt][0] += ma0; s[nt][1] += ma1; s[nt][2] += ma0; s[nt][3] += ma1;
            if (diag) {
                if (c0 > rloc0) s[nt][0] = -1e30f;
                if (c0 + 1 > rloc0) s[nt][1] = -1e30f;
                if (c0 > rloc1) s[nt][2] = -1e30f;
                if (c0 + 1 > rloc1) s[nt][3] = -1e30f;
            }
        }
        float mx0 = -1e30f, mx1 = -1e30f;
#pragma unroll
        for (int nt = 0; nt < 8; nt++) {
            mx0 = fmaxf(mx0, fmaxf(s[nt][0], s[nt][1]));
            mx1 = fmaxf(mx1, fmaxf(s[nt][2], s[nt][3]));
        }
        mx0 = fmaxf(mx0, __shfl_xor_sync(0xffffffff, mx0, 1));
        mx0 = fmaxf(mx0, __shfl_xor_sync(0xffffffff, mx0, 2));
        mx1 = fmaxf(mx1, __shfl_xor_sync(0xffffffff, mx1, 1));
        mx1 = fmaxf(mx1, __shfl_xor_sync(0xffffffff, mx1, 2));
        float mn0 = fmaxf(m0, mx0), mn1 = fmaxf(m1, mx1);
        float cr0 = __expf(m0 - mn0), cr1 = __expf(m1 - mn1);
        float sum0 = 0.f, sum1 = 0.f;
#pragma unroll
        for (int nt = 0; nt < 8; nt++) {
            s[nt][0] = __expf(s[nt][0] - mn0);
            s[nt][1] = __expf(s[nt][1] - mn0);
            s[nt][2] = __expf(s[nt][2] - mn1);
            s[nt][3] = __expf(s[nt][3] - mn1);
            sum0 += s[nt][0] + s[nt][1];
            sum1 += s[nt][2] + s[nt][3];
        }
        sum0 += __shfl_xor_sync(0xffffffff, sum0, 1);
        sum0 += __shfl_xor_sync(0xffffffff, sum0, 2);
        sum1 += __shfl_xor_sync(0xffffffff, sum1, 1);
        sum1 += __shfl_xor_sync(0xffffffff, sum1, 2);
        l0 = l0 * cr0 + sum0;
        l1 = l1 * cr1 + sum1;
        m0 = mn0; m1 = mn1;
#pragma unroll
        for (int i = 0; i < 16; i++) {
            acc[i][0] *= cr0; acc[i][1] *= cr0;
            acc[i][2] *= cr1; acc[i][3] *= cr1;
        }
        uint32_t pf[4][4];
#pragma unroll
        for (int kc = 0; kc < 4; kc++) {
            int j0 = 2 * kc;
            pf[kc][0] = pack2h(s[j0][0], s[j0][1]);
            pf[kc][1] = pack2h(s[j0][2], s[j0][3]);
            pf[kc][2] = pack2h(s[j0 + 1][0], s[j0 + 1][1]);
            pf[kc][3] = pack2h(s[j0 + 1][2], s[j0 + 1][3]);
        }
#pragma unroll
        for (int kc = 0; kc < 4; kc++)
#pragma unroll
            for (int np = 0; np < 8; np++) {
                uint32_t t[4];
                uint32_t addr = vsb + (uint32_t)((kc * 16 + (lane & 15)) * VSTR + np * 16 + (lane >> 4) * 8) * 2;
                ldsm4t(t, addr);
                uint32_t bf0[2] = {t[0], t[1]}, bf1[2] = {t[2], t[3]};
                mma_f16(acc[2 * np], pf[kc], bf0);
                mma_f16(acc[2 * np + 1], pf[kc], bf1);
            }
    }

    float inv0 = 1.f / l0, inv1 = 1.f / l1;
    int r0g = b * SEQLEN + qt * 64 + rloc0;
#pragma unroll
    for (int nt = 0; nt < 16; nt++) {
        int cc = nt * 8 + (lane & 3) * 2;
        size_t o0 = (size_t)r0g * (NH * DV) + h * DV + cc;
        size_t o1 = o0 + 8 * (size_t)(NH * DV);
        O[o0] = __float2half(acc[nt][0] * inv0);
        O[o0 + 1] = __float2half(acc[nt][1] * inv0);
        O[o1] = __float2half(acc[nt][2] * inv1);
        O[o1 + 1] = __float2half(acc[nt][3] * inv1);
    }
}

// ==================== launch ====================
extern "C" void kernel_launch(void* const* d_in, const int* in_sizes, int n_in,
                              void* d_out, int out_size) {
    const float* hidden = (const float*)d_in[0];
    const int* seqmask = (const int*)d_in[1];
    const float* cosT = (const float*)d_in[2];
    const float* sinT = (const float*)d_in[3];
    const float* ln1 = (const float*)d_in[4];
    const float* ln2 = (const float*)d_in[5];
    const float* Wq_down = (const float*)d_in[6];
    const float* Wq_up = (const float*)d_in[7];
    const float* Wkv_down = (const float*)d_in[8];
    const float* Wkv_up = (const float*)d_in[9];
    const float* Wo = (const float*)d_in[10];
    const float* Wgate = (const float*)d_in[11];
    const float* Wup = (const float*)d_in[12];
    const float* Wdown = (const float*)d_in[13];
    float* out = (float*)d_out;

#define SYM(p, s) cudaGetSymbolAddress((void**)&p, s)
    float* p_x;
    SYM(p_x, g_x);
    h16 *hf, *qkvl, *qlnf, *kvnf, *qh, *kvh, *krope, *h2, *ff;
    h16 *Qf, *Kf, *Vf, *atf;
    SYM(hf, g_hf); SYM(qkvl, g_qkvl); SYM(qlnf, g_qlnf); SYM(kvnf, g_kvnf);
    SYM(qh, g_qh); SYM(kvh, g_kvh); SYM(krope, g_krope); SYM(h2, g_h2);
    SYM(ff, g_ff);
    SYM(Qf, g_Qf); SYM(Kf, g_Kf); SYM(Vf, g_Vf); SYM(atf, g_atf);
    h16 *wqkvd, *wqu, *wkvu, *wo, *wgu, *wd;
    SYM(wqkvd, g_wqkvd); SYM(wqu, g_wqu); SYM(wkvu, g_wkvu); SYM(wo, g_wo);
    SYM(wgu, g_wgu); SYM(wd, g_wd);
#undef SYM

    cudaFuncSetAttribute(h1gemm, cudaFuncAttributeMaxDynamicSharedMemorySize, GEMM_SMEM2);
    cudaFuncSetAttribute(attn_mma, cudaFuncAttributeMaxDynamicSharedMemorySize, ATT_SMEM);

    wt_col<<<2048, 256>>>((const float4*)Wq_down, (uint2*)wqkvd,
                          DM * QLORA / 4, QLORA / 4, NQKVD / 4, 0);
    wt_col<<<2048, 256>>>((const float4*)Wkv_down, (uint2*)wqkvd,
                          DM * (KVLORA + ROPE) / 4, (KVLORA + ROPE) / 4, NQKVD / 4, QLORA / 4);
    rmsnorm_h16<<<TOKENS, 256>>>(hidden, ln1, hf, DM, DM);

    // merged q_down + kv_down
    h1gemm<<<dim3((NQKVD + 127) / 128, TOKENS / 128), 256, GEMM_SMEM2>>>(
        hf, wqkvd, nullptr, nullptr, qkvl, 2, TOKENS, NQKVD, DM);

    wt_h1<<<1024, 256>>>((const float4*)Wq_up, (uint2*)wqu, QLORA * NH * DQK / 4);
    rmsnorm_hh<<<TOKENS, 256>>>(qkvl, qlnf, QLORA, NQKVD);
    h1gemm<<<dim3((NH * DQK) / 128, TOKENS / 128), 256, GEMM_SMEM2>>>(
        qlnf, wqu, nullptr, nullptr, qh, 2, TOKENS, NH * DQK, QLORA);
    rope_q_kernel<<<dim3(TOKENS, NH), 128>>>(qh, cosT, sinT, Qf);

    rope_k_kernel<<<TOKENS, 32>>>(qkvl, cosT, sinT, krope);
    rmsnorm_hh<<<TOKENS, 256>>>(qkvl + QLORA, kvnf, KVLORA, NQKVD);

    wt_h1<<<1024, 256>>>((const float4*)Wkv_up, (uint2*)wkvu, KVLORA * NH * (NOPE + DV) / 4);
    h1gemm<<<dim3((NH * (NOPE + DV)) / 128, TOKENS / 128), 256, GEMM_SMEM2>>>(
        kvnf, wkvu, nullptr, nullptr, kvh, 2, TOKENS, NH * (NOPE + DV), KVLORA);
    assemble_kv<<<dim3(TOKENS, NH), DQK + DV>>>(krope, kvh, Kf, Vf);

    wt_h1<<<1024, 256>>>((const float4*)Wo, (uint2*)wo, NH * DV * DM / 4);
    wt_gu<<<2048, 256>>>((const float4*)Wgate, (const float4*)Wup, (uint4*)wgu, DM * DFF / 4);
    wt_h1<<<1024, 256>>>((const float4*)Wdown, (uint2*)wd, DFF * DM / 4);

    attn_mma<<<dim3(SEQLEN / 64, NH, NB), 128, ATT_SMEM>>>(Qf, Kf, Vf, seqmask, atf);

    h1gemm<<<dim3(DM / 128, TOKENS / 128), 256, GEMM_SMEM2>>>(
        atf, wo, hidden, p_x, nullptr, 0, TOKENS, DM, NH * DV);

    rmsnorm_h16<<<TOKENS, 256>>>(p_x, ln2, h2, DM, DM);

    // merged gate+up with fused silu-mul (interleaved columns, N=2*DFF)
    h1gemm<<<dim3((2 * DFF) / 128, TOKENS / 128), 256, GEMM_SMEM2>>>(
        h2, wgu, nullptr, nullptr, ff, 3, TOKENS, 2 * DFF, DM);

    h1gemm<<<dim3(DM / 128, TOKENS / 128), 256, GEMM_SMEM2>>>(
        ff, wd, p_x, out, nullptr, 0, TOKENS, DM, DFF);
}

// round 15
// speedup vs baseline: 1.0749x; 1.0077x over previous
#include <cuda_runtime.h>
#include <cuda_fp16.h>
#include <math.h>
#include <string.h>
#include <stdint.h>

#define TOKENS 4096
#define SEQLEN 2048
#define NB 2
#define DM 2048
#define NH 16
#define QLORA 1536
#define KVLORA 512
#define NOPE 128
#define ROPE 64
#define DQK 192
#define DV 128
#define DFF 8192
#define NQKVD (QLORA + KVLORA + ROPE)   // 2112

typedef __half h16;

// fp32 scratch (residual stream only)
__device__ float g_x[TOKENS * DM];
// fp16 activations
__device__ h16 g_hf[TOKENS * DM];
__device__ h16 g_qkvl[TOKENS * NQKVD];
__device__ h16 g_qlnf[TOKENS * QLORA];
__device__ h16 g_kvnf[TOKENS * KVLORA];
__device__ h16 g_qh[TOKENS * NH * DQK];
__device__ h16 g_kvh[TOKENS * NH * (NOPE + DV)];
__device__ h16 g_krope[TOKENS * ROPE];
__device__ h16 g_h2[TOKENS * DM];
__device__ h16 g_ff[TOKENS * DFF];
__device__ h16 g_Qf[TOKENS * NH * DQK];
__device__ h16 g_Kf[TOKENS * NH * DQK];
__device__ h16 g_Vf[TOKENS * NH * DV];
__device__ h16 g_atf[TOKENS * NH * DV];
// fp16 weights [K][N]
__device__ h16 g_wqkvd[DM * NQKVD];
__device__ h16 g_wqu[QLORA * (NH * DQK)];
__device__ h16 g_wkvu[KVLORA * (NH * (NOPE + DV))];
__device__ h16 g_wo[(NH * DV) * DM];
__device__ h16 g_wgu[DM * (2 * DFF)];
__device__ h16 g_wd[DFF * DM];

// ==================== PTX helpers ====================
__device__ __forceinline__ uint32_t smem_u32(const void* p) {
    uint32_t a;
    asm("{ .reg .u64 t; cvta.to.shared.u64 t, %1; cvt.u32.u64 %0, t; }" : "=r"(a) : "l"(p));
    return a;
}
__device__ __forceinline__ void cp16(uint32_t d, const void* s, int sz) {
    asm volatile("cp.async.cg.shared.global [%0], [%1], 16, %2;" :: "r"(d), "l"(s), "r"(sz) : "memory");
}
__device__ __forceinline__ void cp_commit() { asm volatile("cp.async.commit_group;" ::: "memory"); }
__device__ __forceinline__ void cp_wait0() { asm volatile("cp.async.wait_group 0;" ::: "memory"); }
__device__ __forceinline__ void cp_wait1() { asm volatile("cp.async.wait_group 1;" ::: "memory"); }
__device__ __forceinline__ void ldsm4(uint32_t* r, uint32_t a) {
    asm volatile("ldmatrix.sync.aligned.m8n8.x4.shared.b16 {%0, %1, %2, %3}, [%4];"
                 : "=r"(r[0]), "=r"(r[1]), "=r"(r[2]), "=r"(r[3]) : "r"(a));
}
__device__ __forceinline__ void ldsm4t(uint32_t* r, uint32_t a) {
    asm volatile("ldmatrix.sync.aligned.m8n8.x4.trans.shared.b16 {%0, %1, %2, %3}, [%4];"
                 : "=r"(r[0]), "=r"(r[1]), "=r"(r[2]), "=r"(r[3]) : "r"(a));
}
__device__ __forceinline__ void mma_f16(float* c, const uint32_t* a, const uint32_t* b) {
    asm volatile(
        "mma.sync.aligned.m16n8k16.row.col.f32.f16.f16.f32 "
        "{%0, %1, %2, %3}, {%4, %5, %6, %7}, {%8, %9}, {%0, %1, %2, %3};"
        : "+f"(c[0]), "+f"(c[1]), "+f"(c[2]), "+f"(c[3])
        : "r"(a[0]), "r"(a[1]), "r"(a[2]), "r"(a[3]), "r"(b[0]), "r"(b[1]));
}
__device__ __forceinline__ uint32_t pack2h(float a, float b) {
    __half2 h = __floats2half2_rn(a, b);
    uint32_t u;
    memcpy(&u, &h, 4);
    return u;
}

// ==================== GEMM tiling: BK=64, 2 stages, 2 CTA/SM (round-12 proven) ====================
#define ASTR2 72
#define A2_BYTES (128 * ASTR2 * 2)
#define B2_BYTES (64 * 136 * 2)
#define OFF2_B A2_BYTES
#define STAGE2 (A2_BYTES + B2_BYTES)
#define GEMM_SMEM2 (2 * STAGE2)

// mode 0: C(fp32) = acc (+Df); mode 2: Cs(fp16) = acc;
// mode 3: interleaved gate/up: Cs[rr][cc/2] = silu(v_even)*v_odd (out stride N/2)
__global__ __launch_bounds__(256, 2) void h1gemm(
    const h16* __restrict__ A, const h16* __restrict__ B,
    const float* __restrict__ Df,
    float* __restrict__ C, h16* __restrict__ Cs,
    int mode, int M, int N, int K) {
    extern __shared__ __align__(128) char sm[];
    const int tid = threadIdx.x, wid = tid >> 5, lane = tid & 31;
    const int row0 = blockIdx.y * 128, col0 = blockIdx.x * 128;
    const int m0w = (wid >> 1) * 32, n0w = (wid & 1) * 64;
    const uint32_t smb = smem_u32(sm);

    auto load_stage = [&](int s, int k0) {
        uint32_t sb = smb + (uint32_t)s * STAGE2;
#pragma unroll
        for (int p = 0; p < 4; p++) {
            int idx = tid + p * 256;
            int r = idx >> 3, ch = idx & 7;
            cp16(sb + (uint32_t)(r * 144 + ch * 16),
                 A + (size_t)(row0 + r) * K + k0 + ch * 8, 16);
        }
#pragma unroll
        for (int p = 0; p < 4; p++) {
            int idx = tid + p * 256;
            int r = idx >> 4, ch = idx & 15;
            int col = col0 + ch * 8;
            int valid = (col < N) ? 16 : 0;
            int colc = (col < N) ? col : 0;
            cp16(sb + OFF2_B + (uint32_t)(r * 272 + ch * 16),
                 B + (size_t)(k0 + r) * N + colc, valid);
        }
    };

    float acc[2][8][4];
#pragma unroll
    for (int mi = 0; mi < 2; mi++)
#pragma unroll
        for (int ni = 0; ni < 8; ni++)
#pragma unroll
            for (int j = 0; j < 4; j++) acc[mi][ni][j] = 0.f;

    const int NIT = K >> 6;
    load_stage(0, 0);
    cp_commit();

    const int grp = lane >> 3, w = lane & 7;
    const int a_m = (grp & 1) * 8 + w, a_k = (grp >> 1) * 8;
    const int bt_r = lane & 15, bt_c = (lane >> 4) * 8;

    for (int it = 0; it < NIT; ++it) {
        cp_wait0();
        __syncthreads();
        if (it + 1 < NIT) {
            load_stage((it + 1) & 1, (it + 1) * 64);
            cp_commit();
        }
        uint32_t sb = smb + (uint32_t)(it & 1) * STAGE2;

        uint32_t af[4][2][4];
#pragma unroll
        for (int ks = 0; ks < 4; ks++)
#pragma unroll
            for (int mi = 0; mi < 2; mi++)
                ldsm4(af[ks][mi],
                      sb + (uint32_t)((m0w + mi * 16 + a_m) * ASTR2 + ks * 16 + a_k) * 2);

#pragma unroll
        for (int ks = 0; ks < 4; ks++) {
            uint32_t bf[8][2];
#pragma unroll
            for (int nb = 0; nb < 4; nb++) {
                uint32_t t[4];
                ldsm4t(t, sb + OFF2_B +
                           (uint32_t)((ks * 16 + bt_r) * 136 + n0w + nb * 16 + bt_c) * 2);
                bf[2 * nb][0] = t[0]; bf[2 * nb][1] = t[1];
                bf[2 * nb + 1][0] = t[2]; bf[2 * nb + 1][1] = t[3];
            }
#pragma unroll
            for (int mi = 0; mi < 2; mi++)
#pragma unroll
                for (int ni = 0; ni < 8; ni++) mma_f16(acc[mi][ni], af[ks][mi], bf[ni]);
        }
    }

    __syncthreads();
    const int qr = lane >> 2, qc = (lane & 3) * 2;
#pragma unroll
    for (int mi = 0; mi < 2; mi++)
#pragma unroll
        for (int ni = 0; ni < 8; ni++) {
            int rr = row0 + m0w + mi * 16 + qr;
            int cc = col0 + n0w + ni * 8 + qc;
            if (cc < N) {
                float v0 = acc[mi][ni][0], v1 = acc[mi][ni][1];
                float v2 = acc[mi][ni][2], v3 = acc[mi][ni][3];
                if (mode == 0) {
                    size_t o0 = (size_t)rr * N + cc, o1 = (size_t)(rr + 8) * N + cc;
                    if (Df) { v0 += Df[o0]; v1 += Df[o0 + 1]; v2 += Df[o1]; v3 += Df[o1 + 1]; }
                    C[o0] = v0; C[o0 + 1] = v1; C[o1] = v2; C[o1 + 1] = v3;
                } else if (mode == 2) {
                    size_t o0 = (size_t)rr * N + cc, o1 = (size_t)(rr + 8) * N + cc;
                    Cs[o0] = __float2half(v0); Cs[o0 + 1] = __float2half(v1);
                    Cs[o1] = __float2half(v2); Cs[o1 + 1] = __float2half(v3);
                } else {
                    int half_n = N >> 1;
                    size_t o0 = (size_t)rr * half_n + (cc >> 1);
                    size_t o1 = (size_t)(rr + 8) * half_n + (cc >> 1);
                    Cs[o0] = __float2half((v0 / (1.f + __expf(-v0))) * v1);
                    Cs[o1] = __float2half((v2 / (1.f + __expf(-v2))) * v3);
                }
            }
        }
}

// ==================== weight converters ====================
__global__ void wt_h1(const float4* __restrict__ W, uint2* __restrict__ Bo, int n4) {
    int stride = gridDim.x * blockDim.x;
    int i0 = blockIdx.x * blockDim.x + threadIdx.x;
    for (int i = i0; i < n4; i += stride * 4) {
        float4 v[4];
        int idx[4];
#pragma unroll
        for (int k = 0; k < 4; k++) {
            idx[k] = i + k * stride;
            if (idx[k] < n4) v[k] = W[idx[k]];
        }
#pragma unroll
        for (int k = 0; k < 4; k++) {
            if (idx[k] < n4) {
                h16 h[4];
                h[0] = __float2half(v[k].x);
                h[1] = __float2half(v[k].y);
                h[2] = __float2half(v[k].z);
                h[3] = __float2half(v[k].w);
                uint2 u;
                memcpy(&u, h, 8);
                Bo[idx[k]] = u;
            }
        }
    }
}
__global__ void wt_col(const float4* __restrict__ W, uint2* __restrict__ dst,
                       int n4, int Nsrc4, int Ndst4, int colOff4) {
    int stride = gridDim.x * blockDim.x;
    for (int i = blockIdx.x * blockDim.x + threadIdx.x; i < n4; i += stride) {
        float4 v = W[i];
        int k = i / Nsrc4, c = i - k * Nsrc4;
        h16 h[4];
        h[0] = __float2half(v.x);
        h[1] = __float2half(v.y);
        h[2] = __float2half(v.z);
        h[3] = __float2half(v.w);
        uint2 u;
        memcpy(&u, h, 8);
        dst[(size_t)k * Ndst4 + colOff4 + c] = u;
    }
}
__global__ void wt_gu(const float4* __restrict__ Wg, const float4* __restrict__ Wu,
                      uint4* __restrict__ dst, int n4) {
    int stride = gridDim.x * blockDim.x;
    for (int i = blockIdx.x * blockDim.x + threadIdx.x; i < n4; i += stride) {
        float4 g = Wg[i], u = Wu[i];
        h16 h[8];
        h[0] = __float2half(g.x); h[1] = __float2half(u.x);
        h[2] = __float2half(g.y); h[3] = __float2half(u.y);
        h[4] = __float2half(g.z); h[5] = __float2half(u.z);
        h[6] = __float2half(g.w); h[7] = __float2half(u.w);
        uint4 o;
        memcpy(&o, h, 16);
        dst[i] = o;
    }
}

// ==================== RMSNorm variants ====================
__global__ void rmsnorm_h16(const float* __restrict__ in, const float* __restrict__ w,
                            h16* __restrict__ oh, int cols, int in_ld) {
    int row = blockIdx.x;
    const float* x = in + (size_t)row * in_ld;
    float ss = 0.f;
    for (int c = threadIdx.x; c < cols; c += blockDim.x) { float v = x[c]; ss += v * v; }
    __shared__ float red[256];
    red[threadIdx.x] = ss;
    __syncthreads();
    for (int s = 128; s > 0; s >>= 1) {
        if (threadIdx.x < s) red[threadIdx.x] += red[threadIdx.x + s];
        __syncthreads();
    }
    float scale = 1.0f / sqrtf(red[0] / (float)cols + 1e-5f);
    for (int c = threadIdx.x; c < cols; c += blockDim.x) {
        float v = x[c] * scale;
        if (w) v *= w[c];
        oh[(size_t)row * cols + c] = __float2half(v);
    }
}

// merged q-latent + kv-latent rmsnorm from one qkvl row
__global__ void rmsnorm_qkv(const h16* __restrict__ in, h16* __restrict__ oq,
                            h16* __restrict__ okv) {
    int row = blockIdx.x;
    const h16* x = in + (size_t)row * NQKVD;
    __shared__ float red[256];
    float sq = 0.f;
    for (int c = threadIdx.x; c < QLORA; c += 256) {
        float v = __half2float(x[c]);
        sq += v * v;
    }
    float sk = 0.f;
    for (int c = threadIdx.x; c < KVLORA; c += 256) {
        float v = __half2float(x[QLORA + c]);
        sk += v * v;
    }
    red[threadIdx.x] = sq;
    __syncthreads();
    for (int s = 128; s > 0; s >>= 1) {
        if (threadIdx.x < s) red[threadIdx.x] += red[threadIdx.x + s];
        __syncthreads();
    }
    float scq = 1.0f / sqrtf(red[0] / (float)QLORA + 1e-5f);
    __syncthreads();
    red[threadIdx.x] = sk;
    __syncthreads();
    for (int s = 128; s > 0; s >>= 1) {
        if (threadIdx.x < s) red[threadIdx.x] += red[threadIdx.x + s];
        __syncthreads();
    }
    float sck = 1.0f / sqrtf(red[0] / (float)KVLORA + 1e-5f);
    for (int c = threadIdx.x; c < QLORA; c += 256)
        oq[(size_t)row * QLORA + c] = __float2half(__half2float(x[c]) * scq);
    for (int c = threadIdx.x; c < KVLORA; c += 256)
        okv[(size_t)row * KVLORA + c] = __float2half(__half2float(x[QLORA + c]) * sck);
}

// ==================== RoPE / assemble ====================
__global__ void rope_q_kernel(const h16* __restrict__ qin, const float* __restrict__ cosT,
                              const float* __restrict__ sinT, h16* __restrict__ qout) {
    int t = blockIdx.x, h = blockIdx.y, s = t & (SEQLEN - 1);
    const float sc = 0.07216878364870323f;
    const h16* in = qin + (size_t)t * (NH * DQK) + h * DQK;
    h16* out = qout + (size_t)t * (NH * DQK) + h * DQK;
    int tid = threadIdx.x;
    if (tid < 32) {
        float xr = __half2float(in[NOPE + 2 * tid]), xi = __half2float(in[NOPE + 2 * tid + 1]);
        float c = cosT[(size_t)s * 32 + tid], sn = sinT[(size_t)s * 32 + tid];
        out[2 * tid] = __float2half((xr * c - xi * sn) * sc);
        out[2 * tid + 1] = __float2half((xr * sn + xi * c) * sc);
    }
    out[ROPE + tid] = __float2half(__half2float(in[tid]) * sc);
}

__global__ void rope_k_kernel(const h16* __restrict__ qkvl, const float* __restrict__ cosT,
                              const float* __restrict__ sinT, h16* __restrict__ krope) {
    int t = blockIdx.x, s = t & (SEQLEN - 1), j = threadIdx.x;
    const h16* in = qkvl + (size_t)t * NQKVD + QLORA + KVLORA;
    float xr = __half2float(in[2 * j]), xi = __half2float(in[2 * j + 1]);
    float c = cosT[(size_t)s * 32 + j], sn = sinT[(size_t)s * 32 + j];
    krope[(size_t)t * ROPE + 2 * j] = __float2half(xr * c - xi * sn);
    krope[(size_t)t * ROPE + 2 * j + 1] = __float2half(xr * sn + xi * c);
}

__global__ void assemble_kv(const h16* __restrict__ krope, const h16* __restrict__ kv,
                            h16* __restrict__ K, h16* __restrict__ V) {
    int t = blockIdx.x, h = blockIdx.y, d = threadIdx.x;
    if (d < DQK) {
        h16 v = (d < ROPE) ? krope[(size_t)t * ROPE + d]
                           : kv[(size_t)t * (NH * (NOPE + DV)) + h * NOPE + (d - ROPE)];
        K[(size_t)t * (NH * DQK) + h * DQK + d] = v;
    } else {
        int c = d - DQK;
        V[(size_t)t * (NH * DV) + h * DV + c] =
            kv[(size_t)t * (NH * (NOPE + DV)) + NH * NOPE + h * DV + c];
    }
}

// ==================== fp16 HMMA flash attention: 64-row tile, double-buffered K/V ====================
#define QKSTR 200
#define VSTR 136
#define AQQ_BYTES (64 * QKSTR * 2)            // 25600
#define KSTG (64 * QKSTR * 2)                 // 25600
#define VSTG (64 * VSTR * 2)                  // 17408
#define MSTG 256
#define KVSTG (KSTG + VSTG + MSTG)            // 43264
#define ATT_SMEM3 (AQQ_BYTES + 2 * KVSTG)     // 112128

__global__ __launch_bounds__(128, 2) void attn_mma(
    const h16* __restrict__ Q, const h16* __restrict__ K, const h16* __restrict__ V,
    const int* __restrict__ seqmask, h16* __restrict__ O) {
    extern __shared__ __align__(128) char smc[];
    const int tid = threadIdx.x, wid = tid >> 5, lane = tid & 31;
    const int qt = gridDim.x - 1 - blockIdx.x, h = blockIdx.y, b = blockIdx.z;
    const int warpm = wid * 16;
    const uint32_t smb = smem_u32(smc);
    const uint32_t qsb = smb;

    auto ksb = [&](int s) { return smb + AQQ_BYTES + (uint32_t)s * KVSTG; };
    auto vsb = [&](int s) { return smb + AQQ_BYTES + (uint32_t)s * KVSTG + KSTG; };
    auto mskp = [&](int s) { return (float*)(smc + AQQ_BYTES + s * KVSTG + KSTG + VSTG); };

    auto load_kv = [&](int s, int kt) {
        const h16* Kg = K + ((size_t)(b * SEQLEN + kt * 64) * NH + h) * DQK;
        uint32_t kb = ksb(s);
#pragma unroll
        for (int p = 0; p < 12; p++) {
            int idx = tid + p * 128;
            int r = idx / 24, ch = idx % 24;
            cp16(kb + (uint32_t)(r * QKSTR + ch * 8) * 2, Kg + (size_t)r * (NH * DQK) + ch * 8, 16);
        }
        const h16* Vg = V + (size_t)(b * SEQLEN + kt * 64) * (NH * DV) + h * DV;
        uint32_t vb = vsb(s);
#pragma unroll
        for (int p = 0; p < 8; p++) {
            int idx = tid + p * 128;
            int r = idx >> 4, ch = idx & 15;
            cp16(vb + (uint32_t)(r * VSTR + ch * 8) * 2, Vg + (size_t)r * (NH * DV) + ch * 8, 16);
        }
        if (tid < 64)
            mskp(s)[tid] = (seqmask[b * SEQLEN + kt * 64 + tid] > 0) ? 0.f : -1e30f;
    };

    // Q load (group 0), then KV stage 0 (group 1)
    {
        const h16* Qg = Q + ((size_t)(b * SEQLEN + qt * 64) * NH + h) * DQK;
#pragma unroll
        for (int p = 0; p < 12; p++) {
            int idx = tid + p * 128;
            int r = idx / 24, ch = idx % 24;
            cp16(qsb + (uint32_t)(r * QKSTR + ch * 8) * 2, Qg + (size_t)r * (NH * DQK) + ch * 8, 16);
        }
        cp_commit();
        load_kv(0, 0);
        cp_commit();
        cp_wait1();   // Q done (KV0 may still be in flight)
    }
    __syncthreads();

    const int grp = lane >> 3, w = lane & 7;
    const int a_m = (grp & 1) * 8 + w, a_k = (grp >> 1) * 8;
    const int b_n = (grp >> 1) * 8 + w, b_k = (grp & 1) * 8;

    uint32_t qf[12][4];
#pragma unroll
    for (int kc = 0; kc < 12; kc++)
        ldsm4(qf[kc], qsb + (uint32_t)((warpm + a_m) * QKSTR + kc * 16 + a_k) * 2);

    float acc[16][4];
#pragma unroll
    for (int i = 0; i < 16; i++)
#pragma unroll
        for (int j = 0; j < 4; j++) acc[i][j] = 0.f;
    float m0 = -1e30f, m1 = -1e30f, l0 = 0.f, l1 = 0.f;
    const int rloc0 = warpm + (lane >> 2), rloc1 = rloc0 + 8;

    for (int kt = 0; kt <= qt; kt++) {
        cp_wait0();       // stage kt resident
        __syncthreads();  // stage kt^1 fully consumed by all warps
        if (kt < qt) {
            load_kv((kt + 1) & 1, kt + 1);
            cp_commit();
        }
        int st = kt & 1;
        uint32_t kb = ksb(st), vb = vsb(st);
        float* maskf = mskp(st);

        float s[8][4];
#pragma unroll
        for (int nt = 0; nt < 8; nt++)
#pragma unroll
            for (int j = 0; j < 4; j++) s[nt][j] = 0.f;
#pragma unroll
        for (int kc = 0; kc < 12; kc++)
#pragma unroll
            for (int nb = 0; nb < 4; nb++) {
                uint32_t t[4];
                ldsm4(t, kb + (uint32_t)((nb * 16 + b_n) * QKSTR + kc * 16 + b_k) * 2);
                uint32_t bf0[2] = {t[0], t[1]}, bf1[2] = {t[2], t[3]};
                mma_f16(s[2 * nb], qf[kc], bf0);
                mma_f16(s[2 * nb + 1], qf[kc], bf1);
            }
        bool diag = (kt == qt);
#pragma unroll
        for (int nt = 0; nt < 8; nt++) {
            int c0 = nt * 8 + (lane & 3) * 2;
            float ma0 = maskf[c0], ma1 = maskf[c0 + 1];
            s[nt][0] += ma0; s[nt][1] += ma1; s[nt][2] += ma0; s[nt][3] += ma1;
            if (diag) {
                if (c0 > rloc0) s[nt][0] = -1e30f;
                if (c0 + 1 > rloc0) s[nt][1] = -1e30f;
                if (c0 > rloc1) s[nt][2] = -1e30f;
                if (c0 + 1 > rloc1) s[nt][3] = -1e30f;
            }
        }
        float mx0 = -1e30f, mx1 = -1e30f;
#pragma unroll
        for (int nt = 0; nt < 8; nt++) {
            mx0 = fmaxf(mx0, fmaxf(s[nt][0], s[nt][1]));
            mx1 = fmaxf(mx1, fmaxf(s[nt][2], s[nt][3]));
        }
        mx0 = fmaxf(mx0, __shfl_xor_sync(0xffffffff, mx0, 1));
        mx0 = fmaxf(mx0, __shfl_xor_sync(0xffffffff, mx0, 2));
        mx1 = fmaxf(mx1, __shfl_xor_sync(0xffffffff, mx1, 1));
        mx1 = fmaxf(mx1, __shfl_xor_sync(0xffffffff, mx1, 2));
        float mn0 = fmaxf(m0, mx0), mn1 = fmaxf(m1, mx1);
        float cr0 = __expf(m0 - mn0), cr1 = __expf(m1 - mn1);
        float sum0 = 0.f, sum1 = 0.f;
#pragma unroll
        for (int nt = 0; nt < 8; nt++) {
            s[nt][0] = __expf(s[nt][0] - mn0);
            s[nt][1] = __expf(s[nt][1] - mn0);
            s[nt][2] = __expf(s[nt][2] - mn1);
            s[nt][3] = __expf(s[nt][3] - mn1);
            sum0 += s[nt][0] + s[nt][1];
            sum1 += s[nt][2] + s[nt][3];
        }
        sum0 += __shfl_xor_sync(0xffffffff, sum0, 1);
        sum0 += __shfl_xor_sync(0xffffffff, sum0, 2);
        sum1 += __shfl_xor_sync(0xffffffff, sum1, 1);
        sum1 += __shfl_xor_sync(0xffffffff, sum1, 2);
        l0 = l0 * cr0 + sum0;
        l1 = l1 * cr1 + sum1;
        m0 = mn0; m1 = mn1;
#pragma unroll
        for (int i = 0; i < 16; i++) {
            acc[i][0] *= cr0; acc[i][1] *= cr0;
            acc[i][2] *= cr1; acc[i][3] *= cr1;
        }
        uint32_t pf[4][4];
#pragma unroll
        for (int kc = 0; kc < 4; kc++) {
            int j0 = 2 * kc;
            pf[kc][0] = pack2h(s[j0][0], s[j0][1]);
            pf[kc][1] = pack2h(s[j0][2], s[j0][3]);
            pf[kc][2] = pack2h(s[j0 + 1][0], s[j0 + 1][1]);
            pf[kc][3] = pack2h(s[j0 + 1][2], s[j0 + 1][3]);
        }
#pragma unroll
        for (int kc = 0; kc < 4; kc++)
#pragma unroll
            for (int np = 0; np < 8; np++) {
                uint32_t t[4];
                uint32_t addr = vb + (uint32_t)((kc * 16 + (lane & 15)) * VSTR + np * 16 + (lane >> 4) * 8) * 2;
                ldsm4t(t, addr);
                uint32_t bf0[2] = {t[0], t[1]}, bf1[2] = {t[2], t[3]};
                mma_f16(acc[2 * np], pf[kc], bf0);
                mma_f16(acc[2 * np + 1], pf[kc], bf1);
            }
    }

    float inv0 = 1.f / l0, inv1 = 1.f / l1;
    int r0g = b * SEQLEN + qt * 64 + rloc0;
#pragma unroll
    for (int nt = 0; nt < 16; nt++) {
        int cc = nt * 8 + (lane & 3) * 2;
        size_t o0 = (size_t)r0g * (NH * DV) + h * DV + cc;
        size_t o1 = o0 + 8 * (size_t)(NH * DV);
        O[o0] = __float2half(acc[nt][0] * inv0);
        O[o0 + 1] = __float2half(acc[nt][1] * inv0);
        O[o1] = __float2half(acc[nt][2] * inv1);
        O[o1 + 1] = __float2half(acc[nt][3] * inv1);
    }
}

// ==================== launch ====================
extern "C" void kernel_launch(void* const* d_in, const int* in_sizes, int n_in,
                              void* d_out, int out_size) {
    const float* hidden = (const float*)d_in[0];
    const int* seqmask = (const int*)d_in[1];
    const float* cosT = (const float*)d_in[2];
    const float* sinT = (const float*)d_in[3];
    const float* ln1 = (const float*)d_in[4];
    const float* ln2 = (const float*)d_in[5];
    const float* Wq_down = (const float*)d_in[6];
    const float* Wq_up = (const float*)d_in[7];
    const float* Wkv_down = (const float*)d_in[8];
    const float* Wkv_up = (const float*)d_in[9];
    const float* Wo = (const float*)d_in[10];
    const float* Wgate = (const float*)d_in[11];
    const float* Wup = (const float*)d_in[12];
    const float* Wdown = (const float*)d_in[13];
    float* out = (float*)d_out;

#define SYM(p, s) cudaGetSymbolAddress((void**)&p, s)
    float* p_x;
    SYM(p_x, g_x);
    h16 *hf, *qkvl, *qlnf, *kvnf, *qh, *kvh, *krope, *h2, *ff;
    h16 *Qf, *Kf, *Vf, *atf;
    SYM(hf, g_hf); SYM(qkvl, g_qkvl); SYM(qlnf, g_qlnf); SYM(kvnf, g_kvnf);
    SYM(qh, g_qh); SYM(kvh, g_kvh); SYM(krope, g_krope); SYM(h2, g_h2);
    SYM(ff, g_ff);
    SYM(Qf, g_Qf); SYM(Kf, g_Kf); SYM(Vf, g_Vf); SYM(atf, g_atf);
    h16 *wqkvd, *wqu, *wkvu, *wo, *wgu, *wd;
    SYM(wqkvd, g_wqkvd); SYM(wqu, g_wqu); SYM(wkvu, g_wkvu); SYM(wo, g_wo);
    SYM(wgu, g_wgu); SYM(wd, g_wd);
#undef SYM

    cudaFuncSetAttribute(h1gemm, cudaFuncAttributeMaxDynamicSharedMemorySize, GEMM_SMEM2);
    cudaFuncSetAttribute(attn_mma, cudaFuncAttributeMaxDynamicSharedMemorySize, ATT_SMEM3);

    wt_col<<<2048, 256>>>((const float4*)Wq_down, (uint2*)wqkvd,
                          DM * QLORA / 4, QLORA / 4, NQKVD / 4, 0);
    wt_col<<<2048, 256>>>((const float4*)Wkv_down, (uint2*)wqkvd,
                          DM * (KVLORA + ROPE) / 4, (KVLORA + ROPE) / 4, NQKVD / 4, QLORA / 4);
    rmsnorm_h16<<<TOKENS, 256>>>(hidden, ln1, hf, DM, DM);

    // merged q_down + kv_down
    h1gemm<<<dim3((NQKVD + 127) / 128, TOKENS / 128), 256, GEMM_SMEM2>>>(
        hf, wqkvd, nullptr, nullptr, qkvl, 2, TOKENS, NQKVD, DM);

    wt_h1<<<1024, 256>>>((const float4*)Wq_up, (uint2*)wqu, QLORA * NH * DQK / 4);
    rmsnorm_qkv<<<TOKENS, 256>>>(qkvl, qlnf, kvnf);
    h1gemm<<<dim3((NH * DQK) / 128, TOKENS / 128), 256, GEMM_SMEM2>>>(
        qlnf, wqu, nullptr, nullptr, qh, 2, TOKENS, NH * DQK, QLORA);
    rope_q_kernel<<<dim3(TOKENS, NH), 128>>>(qh, cosT, sinT, Qf);

    rope_k_kernel<<<TOKENS, 32>>>(qkvl, cosT, sinT, krope);

    wt_h1<<<1024, 256>>>((const float4*)Wkv_up, (uint2*)wkvu, KVLORA * NH * (NOPE + DV) / 4);
    h1gemm<<<dim3((NH * (NOPE + DV)) / 128, TOKENS / 128), 256, GEMM_SMEM2>>>(
        kvnf, wkvu, nullptr, nullptr, kvh, 2, TOKENS, NH * (NOPE + DV), KVLORA);
    assemble_kv<<<dim3(TOKENS, NH), DQK + DV>>>(krope, kvh, Kf, Vf);

    wt_h1<<<1024, 256>>>((const float4*)Wo, (uint2*)wo, NH * DV * DM / 4);
    wt_gu<<<2048, 256>>>((const float4*)Wgate, (const float4*)Wup, (uint4*)wgu, DM * DFF / 4);
    wt_h1<<<1024, 256>>>((const float4*)Wdown, (uint2*)wd, DFF * DM / 4);

    attn_mma<<<dim3(SEQLEN / 64, NH, NB), 128, ATT_SMEM3>>>(Qf, Kf, Vf, seqmask, atf);

    h1gemm<<<dim3(DM / 128, TOKENS / 128), 256, GEMM_SMEM2>>>(
        atf, wo, hidden, p_x, nullptr, 0, TOKENS, DM, NH * DV);

    rmsnorm_h16<<<TOKENS, 256>>>(p_x, ln2, h2, DM, DM);

    h1gemm<<<dim3((2 * DFF) / 128, TOKENS / 128), 256, GEMM_SMEM2>>>(
        h2, wgu, nullptr, nullptr, ff, 3, TOKENS, 2 * DFF, DM);

    h1gemm<<<dim3(DM / 128, TOKENS / 128), 256, GEMM_SMEM2>>>(
        ff, wd, p_x, out, nullptr, 0, TOKENS, DM, DFF);
}